// round 2
// baseline (speedup 1.0000x reference)
#include <cuda_runtime.h>

// CrossAttMultiplexer collapses analytically:
//   out[n,i] = v[n,i] * sum_j softmax(...)[n,i,j] = v[n,i] * 1 = s[n,i] * WV[0]
// Pure HBM stream: read s (6.29MB), write out (6.29MB).
//
// R2: latency-bound fix. 4 independent LDG.128 per thread (MLP=4) to hide
// the ~577-cyc DRAM latency; single-wave-ish grid (384 blocks) to kill
// wave-transition overhead seen in R1 (10 waves, DRAM=12.9%).

#define UNROLL 4

__global__ void __launch_bounds__(256)
scale_v4x4_kernel(const float4* __restrict__ s4,
                  const float* __restrict__ WV,
                  float4* __restrict__ out4) {
    const float wv = __ldg(WV);
    // Block covers UNROLL*256 consecutive float4s; loads strided by 256
    // within the block so each of the 4 loads is fully coalesced.
    int base = blockIdx.x * (256 * UNROLL) + threadIdx.x;

    float4 v[UNROLL];
#pragma unroll
    for (int u = 0; u < UNROLL; u++)
        v[u] = s4[base + u * 256];          // front-batched: MLP_p1 = 4
#pragma unroll
    for (int u = 0; u < UNROLL; u++) {
        v[u].x *= wv; v[u].y *= wv; v[u].z *= wv; v[u].w *= wv;
        out4[base + u * 256] = v[u];
    }
}

// Generic fallback (bounds-checked, grid-stride) for sizes that don't tile.
__global__ void scale_generic_kernel(const float* __restrict__ s,
                                     const float* __restrict__ WV,
                                     float* __restrict__ out, int n) {
    const float wv = WV[0];
    for (int i = blockIdx.x * blockDim.x + threadIdx.x; i < n;
         i += gridDim.x * blockDim.x)
        out[i] = s[i] * wv;
}

extern "C" void kernel_launch(void* const* d_in, const int* in_sizes, int n_in,
                              void* d_out, int out_size) {
    // metadata order: x, s, WQ, WK, WV
    const float* s  = (const float*)d_in[1];
    const float* WV = (const float*)d_in[4];
    float* out = (float*)d_out;

    int n = out_size;                 // 1,572,864 expected
    const int tile = 256 * UNROLL * 4;  // elements per block = 4096
    if ((n % tile) == 0) {
        int blocks = n / tile;        // 384
        scale_v4x4_kernel<<<blocks, 256>>>((const float4*)s, WV, (float4*)out);
    } else {
        int blocks = (n + 255) / 256;
        if (blocks > 1184) blocks = 1184;   // 8 blocks/SM cap
        scale_generic_kernel<<<blocks, 256>>>(s, WV, out, n);
    }
}

// round 3
// speedup vs baseline: 1.0047x; 1.0047x over previous
#include <cuda_runtime.h>

// CrossAttMultiplexer collapses analytically:
//   out[n,i] = v[n,i] * sum_j softmax(...)[n,i,j] = s[n,i] * WV[0]
// Pure HBM stream: read s (6.29MB), write out (6.29MB).
//
// R3: maximize occ * MLP product in a single wave.
// 768 blocks x 256 threads x UNROLL 2 float4s = 1,572,864 elements exactly.
// ~5.2 CTAs/SM all resident (one wave), occ ~65%, 2 front-batched LDG.128
// per thread -> ~40KB in flight per SM.

#define UNROLL 2

__global__ void __launch_bounds__(256)
scale_v4x2_kernel(const float4* __restrict__ s4,
                  const float* __restrict__ WV,
                  float4* __restrict__ out4) {
    const float wv = __ldg(WV);
    int base = blockIdx.x * (256 * UNROLL) + threadIdx.x;

    float4 v[UNROLL];
#pragma unroll
    for (int u = 0; u < UNROLL; u++)
        v[u] = s4[base + u * 256];        // front-batched independent loads
#pragma unroll
    for (int u = 0; u < UNROLL; u++) {
        v[u].x *= wv; v[u].y *= wv; v[u].z *= wv; v[u].w *= wv;
        out4[base + u * 256] = v[u];
    }
}

// Generic fallback (bounds-checked, grid-stride) for sizes that don't tile.
__global__ void scale_generic_kernel(const float* __restrict__ s,
                                     const float* __restrict__ WV,
                                     float* __restrict__ out, int n) {
    const float wv = WV[0];
    for (int i = blockIdx.x * blockDim.x + threadIdx.x; i < n;
         i += gridDim.x * blockDim.x)
        out[i] = s[i] * wv;
}

extern "C" void kernel_launch(void* const* d_in, const int* in_sizes, int n_in,
                              void* d_out, int out_size) {
    // metadata order: x, s, WQ, WK, WV
    const float* s  = (const float*)d_in[1];
    const float* WV = (const float*)d_in[4];
    float* out = (float*)d_out;

    int n = out_size;                      // 1,572,864 expected
    const int tile = 256 * UNROLL * 4;     // elements per block = 2048
    if ((n % tile) == 0) {
        int blocks = n / tile;             // 768
        scale_v4x2_kernel<<<blocks, 256>>>((const float4*)s, WV, (float4*)out);
    } else {
        int blocks = (n + 255) / 256;
        if (blocks > 1184) blocks = 1184;
        scale_generic_kernel<<<blocks, 256>>>(s, WV, out, n);
    }
}